// round 15
// baseline (speedup 1.0000x reference)
#include <cuda_runtime.h>
#include <math.h>

#define HW        4096          // H*W
#define CC        3             // channels
#define FF        64            // freq bins
#define BB        32            // batch
#define NSLAB     (BB*CC*FF)    // 6144 slabs
#define HSLAB     (NSLAB/2)     // 3072 slabs per batch-half
#define NUM_KEEP  32
#define BN_EPS    1e-5f

// Scratch (no device allocation allowed -> __device__ globals)
__device__ float g_pooled[NSLAB];
__device__ float g_mask[NSLAB];

// Streaming (evict-first) 16B store for outputs (never re-read).
__device__ __forceinline__ void stcs4(float4* p, float4 v) {
    asm volatile("st.global.cs.v4.f32 [%0], {%1,%2,%3,%4};"
                 :: "l"(p), "f"(v.x), "f"(v.y), "f"(v.z), "f"(v.w)
                 : "memory");
}

// ---------------------------------------------------------------------------
// K1: pool HALF1 (slabs 0..3071) + zero out2-half1. Exact R5 shape (half
// size): 2 slabs/block, 8 front-batched loads + 8 independent zero stores.
// Measured full-size: 27.9us -> expect ~14us. Leaves x-half1 in L2.
// ---------------------------------------------------------------------------
__global__ void pool1_kernel(const float* __restrict__ x,
                             float* __restrict__ out2) {
    const int blk = blockIdx.x;          // half1 slabs 2*blk, 2*blk+1
    const int t = threadIdx.x;
    const size_t base = (size_t)blk * (2 * HW / 4);
    const float4* __restrict__ p = reinterpret_cast<const float4*>(x) + base;
    float4* __restrict__ o2 = reinterpret_cast<float4*>(out2) + base;

    float4 v[8];
#pragma unroll
    for (int i = 0; i < 8; i++)
        v[i] = p[t + i * 256];

    const float4 z = make_float4(0.f, 0.f, 0.f, 0.f);
#pragma unroll
    for (int i = 0; i < 8; i++)
        stcs4(o2 + t + i * 256, z);

    float s0 = 0.f, s1 = 0.f;
#pragma unroll
    for (int i = 0; i < 4; i++)
        s0 += (v[i].x + v[i].y) + (v[i].z + v[i].w);
#pragma unroll
    for (int i = 4; i < 8; i++)
        s1 += (v[i].x + v[i].y) + (v[i].z + v[i].w);

#pragma unroll
    for (int o = 16; o > 0; o >>= 1) {
        s0 += __shfl_xor_sync(0xffffffffu, s0, o);
        s1 += __shfl_xor_sync(0xffffffffu, s1, o);
    }
    __shared__ float ws0[8], ws1[8];
    if ((t & 31) == 0) { ws0[t >> 5] = s0; ws1[t >> 5] = s1; }
    __syncthreads();
    if (t == 0) {
        float a = 0.f, b = 0.f;
#pragma unroll
        for (int i = 0; i < 8; i++) { a += ws0[i]; b += ws1[i]; }
        g_pooled[2 * blk]     = a * (1.0f / HW);
        g_pooled[2 * blk + 1] = b * (1.0f / HW);
    }
}

// ---------------------------------------------------------------------------
// Score for a 16-batch half (b = b0 + blockIdx.x). Same math as before.
// ---------------------------------------------------------------------------
__device__ __forceinline__ float sigmoidf(float v) {
    return 1.0f / (1.0f + expf(-v));
}

__global__ void score_kernel(const float* __restrict__ conv_w,
                             const float* __restrict__ conv_b,
                             const float* __restrict__ fc_w,
                             const float* __restrict__ fc_b,
                             const float* __restrict__ conv1_w,
                             const float* __restrict__ conv1_b,
                             const float* __restrict__ convr_w,
                             const float* __restrict__ convr_b,
                             const float* __restrict__ convl_w,
                             const float* __restrict__ convl_b,
                             const float* __restrict__ bn_gamma,
                             const float* __restrict__ bn_beta,
                             const float* __restrict__ bn_mean,
                             const float* __restrict__ bn_var,
                             const float* __restrict__ a_ptr,
                             int b0) {
    const int b = b0 + blockIdx.x;
    const int g = threadIdx.x;   // 0..63

    __shared__ float pooled[CC][FF];
    __shared__ float xconv[CC][FF];
    __shared__ float scores[CC][FF];
    __shared__ float fin[CC][FF];
    __shared__ float xrc[CC][2][8];
    __shared__ float xrc2[CC][2][8];
    __shared__ float ar[CC][8];
    __shared__ float al[CC][8];

#pragma unroll
    for (int c = 0; c < CC; c++)
        pooled[c][g] = g_pooled[(b * CC + c) * FF + g];
    __syncthreads();

#pragma unroll
    for (int c = 0; c < CC; c++) {
        float s = conv_b[g];
        for (int f = 0; f < FF; f++)
            s = fmaf(pooled[c][f], conv_w[g * FF + f], s);
        xconv[c][g] = s;
    }
    __syncthreads();

#pragma unroll
    for (int c = 0; c < CC; c++) {
        float s = fc_b[g];
        for (int f = 0; f < FF; f++)
            s = fmaf(xconv[c][f], fc_w[g * FF + f], s);
        scores[c][g] = sigmoidf(s);
    }

    if (g < CC * 8) {
        int c = g / 8, i = g % 8;
        float r = 0.f, co = 0.f;
#pragma unroll
        for (int j = 0; j < 8; j++) {
            r  += pooled[c][i * 8 + j];
            co += pooled[c][j * 8 + i];
        }
        xrc[c][0][i] = r * 0.125f;
        xrc[c][1][i] = co * 0.125f;
    }
    __syncthreads();

    if (g < CC * 8) {
        int d = g / 8, i = g % 8;
        float inv = rsqrtf(bn_var[d] + BN_EPS);
#pragma unroll
        for (int s2 = 0; s2 < 2; s2++) {
            float v = conv1_b[d];
#pragma unroll
            for (int c = 0; c < CC; c++)
                v = fmaf(xrc[c][s2][i], conv1_w[d * CC + c], v);
            v = (v - bn_mean[d]) * inv;
            v = v * bn_gamma[d] + bn_beta[d];
            xrc2[d][s2][i] = sigmoidf(v);
        }
    }
    __syncthreads();

    if (g < CC * 8) {
        int d = g / 8, i = g % 8;
        float vr = convr_b[d], vl = convl_b[d];
#pragma unroll
        for (int c = 0; c < CC; c++) {
            vr = fmaf(xrc2[c][0][i], convr_w[d * CC + c], vr);
            vl = fmaf(xrc2[c][1][i], convl_w[d * CC + c], vl);
        }
        ar[d][i] = sigmoidf(vr);
        al[d][i] = sigmoidf(vl);
    }
    __syncthreads();

    const float a = *a_ptr;
    const int i = g >> 3, j = g & 7;
#pragma unroll
    for (int c = 0; c < CC; c++)
        fin[c][g] = a * ar[c][i] * al[c][j] + (1.0f - a) * scores[c][g];
    __syncthreads();

    // top-32 via stable rank (ties -> lower index wins, matches jax top_k)
#pragma unroll
    for (int c = 0; c < CC; c++) {
        float v = fin[c][g];
        int rank = 0;
        for (int f = 0; f < FF; f++) {
            float u = fin[c][f];
            rank += (u > v) || (u == v && f < g);
        }
        g_mask[(b * CC + c) * FF + g] = (rank < NUM_KEEP) ? 1.0f : 0.0f;
    }
}

// ---------------------------------------------------------------------------
// K3 (fused): per block blk in 0..3071:
//   - pool-read half2 slab (3072+blk): 4 front-batched DRAM loads + reduce
//   - prune half1 slab blk: copy (4 L2 loads, x-half1 fresh from K1) or zero
//   - zero out2-half2 slab (3072+blk): 4 independent zero stores
// Issue order: DRAM loads -> L2 loads -> independent zero stores -> copy
// stores -> reduction. 100MB W + 75MB R; writes at cap, reads hidden.
// ---------------------------------------------------------------------------
__global__ void fusedA_kernel(const float* __restrict__ x,
                              float* __restrict__ out1,
                              float* __restrict__ out2) {
    const int blk = blockIdx.x;          // 0..3071
    const int t = threadIdx.x;           // 0..255
    const int ps = blk;                  // prune slab (half1)
    const int qs = HSLAB + blk;          // pool slab (half2)

    const float4* __restrict__ p = reinterpret_cast<const float4*>(x);
    float4* __restrict__ o1 = reinterpret_cast<float4*>(out1);
    float4* __restrict__ o2 = reinterpret_cast<float4*>(out2);

    const size_t qb = (size_t)qs * (HW / 4) + t;
    const size_t pb = (size_t)ps * (HW / 4) + t;

    // 1) pool loads (DRAM, longest latency) first
    float4 v[4];
#pragma unroll
    for (int i = 0; i < 4; i++)
        v[i] = p[qb + i * 256];

    // 2) prune loads (L2-resident x-half1)
    const bool keep = (g_mask[ps] != 0.0f);
    const float4 z = make_float4(0.f, 0.f, 0.f, 0.f);
    float4 c[4] = {z, z, z, z};
    if (keep) {
#pragma unroll
        for (int i = 0; i < 4; i++)
            c[i] = p[pb + i * 256];
    }

    // 3) independent zero stores (out2-half2): fill write pipe now
#pragma unroll
    for (int i = 0; i < 4; i++)
        stcs4(o2 + qb + i * 256, z);

    // 4) prune stores (dep on fast L2 loads)
#pragma unroll
    for (int i = 0; i < 4; i++)
        stcs4(o1 + pb + i * 256, c[i]);

    // 5) pool reduction (dep on DRAM loads, at the end)
    float s = 0.f;
#pragma unroll
    for (int i = 0; i < 4; i++)
        s += (v[i].x + v[i].y) + (v[i].z + v[i].w);
#pragma unroll
    for (int o = 16; o > 0; o >>= 1)
        s += __shfl_xor_sync(0xffffffffu, s, o);

    __shared__ float ws[8];
    if ((t & 31) == 0) ws[t >> 5] = s;
    __syncthreads();
    if (t == 0) {
        float tot = 0.f;
#pragma unroll
        for (int i = 0; i < 8; i++) tot += ws[i];
        g_pooled[qs] = tot * (1.0f / HW);
    }
}

// ---------------------------------------------------------------------------
// K5: prune half2 (slabs 3072..6143). x-half2 was read most recently by K3
// -> L2-resident (R4 regime, ~11-14us for 50W+25R).
// ---------------------------------------------------------------------------
__global__ void pruneB_kernel(const float* __restrict__ x,
                              float* __restrict__ out1) {
    const int slab = HSLAB + blockIdx.x;
    const int t = threadIdx.x;
    const size_t b = (size_t)slab * (HW / 4) + t;
    const float4* __restrict__ p = reinterpret_cast<const float4*>(x);
    float4* __restrict__ o = reinterpret_cast<float4*>(out1);

    const bool keep = (g_mask[slab] != 0.0f);
    if (keep) {
        float4 v[4];
#pragma unroll
        for (int i = 0; i < 4; i++)
            v[i] = p[b + i * 256];
#pragma unroll
        for (int i = 0; i < 4; i++)
            stcs4(o + b + i * 256, v[i]);
    } else {
        const float4 z = make_float4(0.f, 0.f, 0.f, 0.f);
#pragma unroll
        for (int i = 0; i < 4; i++)
            stcs4(o + b + i * 256, z);
    }
}

// ---------------------------------------------------------------------------
extern "C" void kernel_launch(void* const* d_in, const int* in_sizes, int n_in,
                              void* d_out, int out_size) {
    const float* x_freq  = (const float*)d_in[0];
    const float* conv_w  = (const float*)d_in[1];
    const float* conv_b  = (const float*)d_in[2];
    const float* fc_w    = (const float*)d_in[3];
    const float* fc_b    = (const float*)d_in[4];
    const float* conv1_w = (const float*)d_in[5];
    const float* conv1_b = (const float*)d_in[6];
    const float* convr_w = (const float*)d_in[7];
    const float* convr_b = (const float*)d_in[8];
    const float* convl_w = (const float*)d_in[9];
    const float* convl_b = (const float*)d_in[10];
    const float* bn_gamma = (const float*)d_in[11];
    const float* bn_beta  = (const float*)d_in[12];
    const float* bn_mean  = (const float*)d_in[13];
    const float* bn_var   = (const float*)d_in[14];
    const float* a_scalar = (const float*)d_in[15];

    float* out1 = (float*)d_out;                       // x_pruned
    float* out2 = (float*)d_out + (size_t)NSLAB * HW;  // x_pruned_2k (zeros)

    // Half 1: pool + zero out2-half1
    pool1_kernel<<<HSLAB / 2, 256>>>(x_freq, out2);
    score_kernel<<<BB / 2, FF>>>(conv_w, conv_b, fc_w, fc_b,
                                 conv1_w, conv1_b, convr_w, convr_b,
                                 convl_w, convl_b,
                                 bn_gamma, bn_beta, bn_mean, bn_var,
                                 a_scalar, 0);
    // Fused: prune half1 + pool half2 + zero out2-half2
    fusedA_kernel<<<HSLAB, 256>>>(x_freq, out1, out2);
    score_kernel<<<BB / 2, FF>>>(conv_w, conv_b, fc_w, fc_b,
                                 conv1_w, conv1_b, convr_w, convr_b,
                                 convl_w, convl_b,
                                 bn_gamma, bn_beta, bn_mean, bn_var,
                                 a_scalar, BB / 2);
    // Prune half2 (L2 reads)
    pruneB_kernel<<<HSLAB, 256>>>(x_freq, out1);
}

// round 16
// speedup vs baseline: 1.3060x; 1.3060x over previous
#include <cuda_runtime.h>
#include <math.h>

#define HW        4096          // H*W
#define CC        3             // channels
#define FF        64            // freq bins
#define BB        32            // batch
#define NSLAB     (BB*CC*FF)    // 6144 (b,c,f) slabs
#define NUM_KEEP  32
#define BN_EPS    1e-5f
#define STHREADS  (CC*FF)       // 192 score threads

// Scratch (no device allocation allowed -> __device__ globals)
__device__ float g_pooled[NSLAB];
__device__ float g_mask[NSLAB];

// Streaming (evict-first) 16B store: outputs are never re-read.
__device__ __forceinline__ void stcs4(float4* p, float4 v) {
    asm volatile("st.global.cs.v4.f32 [%0], {%1,%2,%3,%4};"
                 :: "l"(p), "f"(v.x), "f"(v.y), "f"(v.z), "f"(v.w)
                 : "memory");
}

// ---------------------------------------------------------------------------
// Kernel A: mean over H*W per slab. READ ONLY (R3 shape, measured 18.9us).
// One block per 2 slabs; 8 front-batched float4 loads per thread.
// ---------------------------------------------------------------------------
__global__ void pool_kernel(const float* __restrict__ x) {
    const int blk = blockIdx.x;          // slabs 2*blk, 2*blk+1
    const int t = threadIdx.x;           // 0..255
    const float4* __restrict__ p =
        reinterpret_cast<const float4*>(x) + (size_t)blk * (2 * HW / 4);

    float4 v[8];
#pragma unroll
    for (int i = 0; i < 8; i++)
        v[i] = p[t + i * 256];

    float s0 = 0.f, s1 = 0.f;
#pragma unroll
    for (int i = 0; i < 4; i++)
        s0 += (v[i].x + v[i].y) + (v[i].z + v[i].w);
#pragma unroll
    for (int i = 4; i < 8; i++)
        s1 += (v[i].x + v[i].y) + (v[i].z + v[i].w);

#pragma unroll
    for (int o = 16; o > 0; o >>= 1) {
        s0 += __shfl_xor_sync(0xffffffffu, s0, o);
        s1 += __shfl_xor_sync(0xffffffffu, s1, o);
    }

    __shared__ float ws0[8], ws1[8];
    if ((t & 31) == 0) { ws0[t >> 5] = s0; ws1[t >> 5] = s1; }
    __syncthreads();
    if (t == 0) {
        float a = 0.f, b = 0.f;
#pragma unroll
        for (int i = 0; i < 8; i++) { a += ws0[i]; b += ws1[i]; }
        g_pooled[2 * blk]     = a * (1.0f / HW);
        g_pooled[2 * blk + 1] = b * (1.0f / HW);
    }
}

// ---------------------------------------------------------------------------
// Kernel B (OPTIMIZED): scoring + top-32 mask. 192 threads = one (c,g) pair
// each. Weights staged in smem TRANSPOSED (coalesced LDG, conflict-free LDS).
// Accumulation order per output is unchanged (bitwise-identical results).
// ---------------------------------------------------------------------------
__device__ __forceinline__ float sigmoidf(float v) {
    return 1.0f / (1.0f + expf(-v));
}

__global__ void __launch_bounds__(STHREADS)
score_kernel(const float* __restrict__ conv_w,
             const float* __restrict__ conv_b,
             const float* __restrict__ fc_w,
             const float* __restrict__ fc_b,
             const float* __restrict__ conv1_w,
             const float* __restrict__ conv1_b,
             const float* __restrict__ convr_w,
             const float* __restrict__ convr_b,
             const float* __restrict__ convl_w,
             const float* __restrict__ convl_b,
             const float* __restrict__ bn_gamma,
             const float* __restrict__ bn_beta,
             const float* __restrict__ bn_mean,
             const float* __restrict__ bn_var,
             const float* __restrict__ a_ptr) {
    const int b   = blockIdx.x;
    const int tid = threadIdx.x;     // 0..191
    const int c   = tid / FF;        // 0..2
    const int g   = tid % FF;        // 0..63

    __shared__ float wT[FF][FF + 1]; // conv_w transposed: wT[f][g]
    __shared__ float fT[FF][FF + 1]; // fc_w transposed
    __shared__ float pooled[CC][FF];
    __shared__ float xconv[CC][FF];
    __shared__ float scores[CC][FF];
    __shared__ float fin[CC][FF];
    __shared__ float xrc[CC][2][8];
    __shared__ float xrc2[CC][2][8];
    __shared__ float ar[CC][8];
    __shared__ float al[CC][8];

    // Stage weights: coalesced global reads, transposed smem writes.
    for (int idx = tid; idx < FF * FF; idx += STHREADS) {
        const int row = idx >> 6, col = idx & 63;
        wT[col][row] = conv_w[idx];
        fT[col][row] = fc_w[idx];
    }
    pooled[c][g] = g_pooled[(b * CC + c) * FF + g];
    __syncthreads();

    // x_conv[c][g] = sum_f pooled[c][f] * conv_w[g][f] + conv_b[g]
    {
        float s = conv_b[g];
#pragma unroll
        for (int f = 0; f < FF; f++)
            s = fmaf(pooled[c][f], wT[f][g], s);
        xconv[c][g] = s;
    }
    __syncthreads();

    // scores[c][g] = sigmoid(sum_f xconv[c][f] * fc_w[g][f] + fc_b[g])
    {
        float s = fc_b[g];
#pragma unroll
        for (int f = 0; f < FF; f++)
            s = fmaf(xconv[c][f], fT[f][g], s);
        scores[c][g] = sigmoidf(s);
    }

    // row / col means of pooled viewed as 8x8
    if (tid < CC * 8) {
        const int cc = tid / 8, i = tid % 8;
        float r = 0.f, co = 0.f;
#pragma unroll
        for (int j = 0; j < 8; j++) {
            r  += pooled[cc][i * 8 + j];
            co += pooled[cc][j * 8 + i];
        }
        xrc[cc][0][i] = r * 0.125f;
        xrc[cc][1][i] = co * 0.125f;
    }
    __syncthreads();

    // conv1 (mixes channels) + BN + sigmoid
    if (tid < CC * 8) {
        const int d = tid / 8, i = tid % 8;
        const float inv = rsqrtf(bn_var[d] + BN_EPS);
#pragma unroll
        for (int s2 = 0; s2 < 2; s2++) {
            float v = conv1_b[d];
#pragma unroll
            for (int cc = 0; cc < CC; cc++)
                v = fmaf(xrc[cc][s2][i], conv1_w[d * CC + cc], v);
            v = (v - bn_mean[d]) * inv;
            v = v * bn_gamma[d] + bn_beta[d];
            xrc2[d][s2][i] = sigmoidf(v);
        }
    }
    __syncthreads();

    // a_r, a_l (channel-mixing 1x1 convs + sigmoid)
    if (tid < CC * 8) {
        const int d = tid / 8, i = tid % 8;
        float vr = convr_b[d], vl = convl_b[d];
#pragma unroll
        for (int cc = 0; cc < CC; cc++) {
            vr = fmaf(xrc2[cc][0][i], convr_w[d * CC + cc], vr);
            vl = fmaf(xrc2[cc][1][i], convl_w[d * CC + cc], vl);
        }
        ar[d][i] = sigmoidf(vr);
        al[d][i] = sigmoidf(vl);
    }
    __syncthreads();

    // final = a * (a_r outer a_l) + (1-a) * scores
    {
        const float a = *a_ptr;
        const int i = g >> 3, j = g & 7;
        fin[c][g] = a * ar[c][i] * al[c][j] + (1.0f - a) * scores[c][g];
    }
    __syncthreads();

    // top-32 via stable rank (ties -> lower index wins, matches jax top_k)
    {
        const float v = fin[c][g];
        int rank = 0;
#pragma unroll
        for (int f = 0; f < FF; f++) {
            const float u = fin[c][f];
            rank += (u > v) || (u == v && f < g);
        }
        g_mask[(b * CC + c) * FF + g] = (rank < NUM_KEEP) ? 1.0f : 0.0f;
    }
}

// ---------------------------------------------------------------------------
// Kernel C (R3 shape): writes BOTH outputs with streaming stores.
// slab < NSLAB: x_pruned (copy if kept, zeros if dropped).
// slab >= NSLAB: x_pruned_2k zero-fill. 256 threads x 4 float4 per slab.
// ---------------------------------------------------------------------------
__global__ void prune_kernel(const float* __restrict__ x,
                             float* __restrict__ out) {
    const int slab = blockIdx.x;
    const int t = threadIdx.x;
    float4* __restrict__ o =
        reinterpret_cast<float4*>(out) + (size_t)slab * (HW / 4);

    bool keep = false;
    if (slab < NSLAB) keep = (g_mask[slab] != 0.0f);

    if (keep) {
        const float4* __restrict__ p =
            reinterpret_cast<const float4*>(x) + (size_t)slab * (HW / 4);
        float4 v[4];
#pragma unroll
        for (int i = 0; i < 4; i++)
            v[i] = p[t + i * 256];
#pragma unroll
        for (int i = 0; i < 4; i++)
            stcs4(o + t + i * 256, v[i]);
    } else {
        const float4 z = make_float4(0.f, 0.f, 0.f, 0.f);
#pragma unroll
        for (int i = 0; i < 4; i++)
            stcs4(o + t + i * 256, z);
    }
}

// ---------------------------------------------------------------------------
extern "C" void kernel_launch(void* const* d_in, const int* in_sizes, int n_in,
                              void* d_out, int out_size) {
    const float* x_freq  = (const float*)d_in[0];
    const float* conv_w  = (const float*)d_in[1];
    const float* conv_b  = (const float*)d_in[2];
    const float* fc_w    = (const float*)d_in[3];
    const float* fc_b    = (const float*)d_in[4];
    const float* conv1_w = (const float*)d_in[5];
    const float* conv1_b = (const float*)d_in[6];
    const float* convr_w = (const float*)d_in[7];
    const float* convr_b = (const float*)d_in[8];
    const float* convl_w = (const float*)d_in[9];
    const float* convl_b = (const float*)d_in[10];
    const float* bn_gamma = (const float*)d_in[11];
    const float* bn_beta  = (const float*)d_in[12];
    const float* bn_mean  = (const float*)d_in[13];
    const float* bn_var   = (const float*)d_in[14];
    const float* a_scalar = (const float*)d_in[15];

    float* out = (float*)d_out;

    pool_kernel<<<NSLAB / 2, 256>>>(x_freq);
    score_kernel<<<BB, STHREADS>>>(conv_w, conv_b, fc_w, fc_b,
                                   conv1_w, conv1_b, convr_w, convr_b,
                                   convl_w, convl_b,
                                   bn_gamma, bn_beta, bn_mean, bn_var,
                                   a_scalar);
    prune_kernel<<<2 * NSLAB, 256>>>(x_freq, out);
}